// round 4
// baseline (speedup 1.0000x reference)
#include <cuda_runtime.h>
#include <cstdint>

#define FULLM 0xffffffffu

constexpr int Bsz  = 16384;
constexpr int Sdim = 24;
constexpr int Adim = 4;
constexpr int Tlen = 40;

// ---- shared memory layout (float offsets) ----
#define OFF_WSIN   0
#define OFF_WSREC  3072
#define OFF_WAIN   7168
#define OFF_WARC1  7680
#define OFF_WC2    15872
#define OFF_WRO    24064
#define SMEM_FLOATS 24128

__device__ unsigned g_ticket;

__global__ void reset_ticket_kernel(unsigned start) { g_ticket = start; }

__global__ void __launch_bounds__(512, 2)
snn_kernel(const float* __restrict__ state, const float* __restrict__ action,
           const float* __restrict__ Wsin, const float* __restrict__ Wsrec,
           const float* __restrict__ Wain, const float* __restrict__ Warec,
           const float* __restrict__ Wcin, const float* __restrict__ Wcrec,
           const float* __restrict__ Wro, float* __restrict__ out)
{
    extern __shared__ float smem[];
    const int tid = threadIdx.x;

    // ---- cooperative weight load / transpose (exact fp32) ----
    for (int idx = tid; idx < 48 * 32; idx += 512) {
        int k = idx >> 5, l = idx & 31;
        smem[OFF_WSIN + k * 64 + 2 * l]     = Wsin[l * 48 + k];
        smem[OFF_WSIN + k * 64 + 2 * l + 1] = Wsin[(l + 32) * 48 + k];
    }
    for (int idx = tid; idx < 64 * 32; idx += 512) {
        int k = idx >> 5, l = idx & 31;
        smem[OFF_WSREC + k * 64 + 2 * l]     = Wsrec[l * 64 + k];
        smem[OFF_WSREC + k * 64 + 2 * l + 1] = Wsrec[(l + 32) * 64 + k];
        float4 w4;
        w4.x = Warec[l * 64 + k];
        w4.y = Warec[(l + 32) * 64 + k];
        w4.z = Wcin[l * 128 + k];
        w4.w = Wcin[(l + 32) * 128 + k];
        reinterpret_cast<float4*>(smem + OFF_WARC1)[k * 32 + l] = w4;
        float4 c4;
        c4.x = Wcin[l * 128 + 64 + k];
        c4.y = Wcin[(l + 32) * 128 + 64 + k];
        c4.z = Wcrec[l * 64 + k];
        c4.w = Wcrec[(l + 32) * 64 + k];
        reinterpret_cast<float4*>(smem + OFF_WC2)[k * 32 + l] = c4;
    }
    for (int idx = tid; idx < 8 * 32; idx += 512) {
        int k = idx >> 5, l = idx & 31;
        smem[OFF_WAIN + k * 64 + 2 * l]     = Wain[l * 8 + k];
        smem[OFF_WAIN + k * 64 + 2 * l + 1] = Wain[(l + 32) * 8 + k];
    }
    if (tid < 64) smem[OFF_WRO + tid] = Wro[tid];
    __syncthreads();

    const int lane = tid & 31;
    const float2* ws_in  = reinterpret_cast<const float2*>(smem + OFF_WSIN)  + lane;
    const float2* ws_rec = reinterpret_cast<const float2*>(smem + OFF_WSREC) + lane;
    const float2* wa_in  = reinterpret_cast<const float2*>(smem + OFF_WAIN)  + lane;
    const float4* warc1  = reinterpret_cast<const float4*>(smem + OFF_WARC1) + lane;
    const float4* wc2    = reinterpret_cast<const float4*>(smem + OFF_WC2)   + lane;
    const float*  w_ro   = smem + OFF_WRO;

    unsigned b = blockIdx.x * 16u + (unsigned)(tid >> 5);

    while (b < (unsigned)Bsz) {
        const float* srow = state  + (size_t)b * Sdim;
        const float* arow = action + (size_t)b * Adim;

        float c0, c1;
        if (lane < 24) c0 = fmaxf(__fmul_rn(50.f, srow[lane]), 0.f);
        else           c0 = fmaxf(__fmul_rn(-50.f, srow[lane - 24]), 0.f);
        if (lane < 16)      c1 = fmaxf(__fmul_rn(-50.f, srow[8 + lane]), 0.f);
        else if (lane < 20) c1 = fmaxf(__fmul_rn(50.f, arow[lane - 16]), 0.f);
        else if (lane < 24) c1 = fmaxf(__fmul_rn(-50.f, arow[lane - 20]), 0.f);
        else                c1 = 0.f;

        float ve0 = 0.f, ve1 = 0.f;
        float v0 = 0.f, v1 = 0.f;
        float i0 = 0.f, i1 = 0.f;
        unsigned long long zm = 0ull;
        float vli = 0.f, ili = 0.f;
        float vmax = -3.0e38f;

        for (int t = 0; t < Tlen; t++) {
            // ---- encoder step (FMA-contracted like XLA) ----
            ve0 = __fmaf_rn(0.1f, __fsub_rn(c0, ve0), ve0);
            bool s0 = __fsub_rn(ve0, 1.0f) > 0.0f; if (s0) ve0 = 0.f;
            ve1 = __fmaf_rn(0.1f, __fsub_rn(c1, ve1), ve1);
            bool s1 = (lane < 24) && (__fsub_rn(ve1, 1.0f) > 0.0f); if (s1) ve1 = 0.f;
            unsigned mlo = __ballot_sync(FULLM, s0);
            unsigned mhi = __ballot_sync(FULLM, s1);
            unsigned long long xs = (unsigned long long)mlo |
                                    ((unsigned long long)(mhi & 0xFFFFu) << 32);
            unsigned xa = (mhi >> 16) & 0xFFu;

            // ---- lif1 ----
            float id0 = __fmaf_rn(-0.2f, i0, i0);
            float id1 = __fmaf_rn(-0.2f, i1, i1);
            float vd0 = __fmaf_rn(0.1f, __fsub_rn(i0, v0), v0);
            float vd1 = __fmaf_rn(0.1f, __fsub_rn(i1, v1), v1);
            bool zs0 = __fsub_rn(vd0, 1.0f) > 0.0f; v0 = zs0 ? 0.f : vd0;
            bool zs1 = __fsub_rn(vd1, 1.0f) > 0.0f; v1 = zs1 ? 0.f : vd1;

            float a0 = 0.f, a1 = 0.f;
            {
                unsigned m = (unsigned)xs;
                while (m) { int k = __ffs(m) - 1; m &= m - 1;
                            float2 w = ws_in[k * 32];
                            a0 = __fadd_rn(a0, w.x); a1 = __fadd_rn(a1, w.y); }
                m = (unsigned)(xs >> 32);
                while (m) { int k = __ffs(m) - 1 + 32; m &= m - 1;
                            float2 w = ws_in[k * 32];
                            a0 = __fadd_rn(a0, w.x); a1 = __fadd_rn(a1, w.y); }
            }
            float r0 = 0.f, r1 = 0.f;
            {
                unsigned m = (unsigned)zm;
                while (m) { int k = __ffs(m) - 1; m &= m - 1;
                            float2 w = ws_rec[k * 32];
                            r0 = __fadd_rn(r0, w.x); r1 = __fadd_rn(r1, w.y); }
                m = (unsigned)(zm >> 32);
                while (m) { int k = __ffs(m) - 1 + 32; m &= m - 1;
                            float2 w = ws_rec[k * 32];
                            r0 = __fadd_rn(r0, w.x); r1 = __fadd_rn(r1, w.y); }
            }
            i0 = __fadd_rn(__fadd_rn(id0, a0), r0);
            i1 = __fadd_rn(__fadd_rn(id1, a1), r1);

            unsigned zslo = __ballot_sync(FULLM, zs0);
            unsigned zshi = __ballot_sync(FULLM, zs1);
            unsigned long long zsm = (unsigned long long)zslo | ((unsigned long long)zshi << 32);

            // ---- lif2 (+ gather Wcin[:, :64]·z_s for lif3) ----
            id0 = __fmaf_rn(-0.2f, i0, i0);
            id1 = __fmaf_rn(-0.2f, i1, i1);
            vd0 = __fmaf_rn(0.1f, __fsub_rn(i0, v0), v0);
            vd1 = __fmaf_rn(0.1f, __fsub_rn(i1, v1), v1);
            bool za0 = __fsub_rn(vd0, 1.0f) > 0.0f; v0 = za0 ? 0.f : vd0;
            bool za1 = __fsub_rn(vd1, 1.0f) > 0.0f; v1 = za1 ? 0.f : vd1;

            float p0 = 0.f, p1 = 0.f;
            {
                unsigned m = xa;
                while (m) { int k = __ffs(m) - 1; m &= m - 1;
                            float2 w = wa_in[k * 32];
                            p0 = __fadd_rn(p0, w.x); p1 = __fadd_rn(p1, w.y); }
            }
            float q0 = 0.f, q1 = 0.f, u0 = 0.f, u1 = 0.f;
            {
                unsigned m = (unsigned)zsm;
                while (m) { int k = __ffs(m) - 1; m &= m - 1;
                            float4 w = warc1[k * 32];
                            q0 = __fadd_rn(q0, w.x); q1 = __fadd_rn(q1, w.y);
                            u0 = __fadd_rn(u0, w.z); u1 = __fadd_rn(u1, w.w); }
                m = (unsigned)(zsm >> 32);
                while (m) { int k = __ffs(m) - 1 + 32; m &= m - 1;
                            float4 w = warc1[k * 32];
                            q0 = __fadd_rn(q0, w.x); q1 = __fadd_rn(q1, w.y);
                            u0 = __fadd_rn(u0, w.z); u1 = __fadd_rn(u1, w.w); }
            }
            i0 = __fadd_rn(__fadd_rn(id0, p0), q0);
            i1 = __fadd_rn(__fadd_rn(id1, p1), q1);

            unsigned zalo = __ballot_sync(FULLM, za0);
            unsigned zahi = __ballot_sync(FULLM, za1);
            unsigned long long zam = (unsigned long long)zalo | ((unsigned long long)zahi << 32);

            // ---- lif3 ----
            id0 = __fmaf_rn(-0.2f, i0, i0);
            id1 = __fmaf_rn(-0.2f, i1, i1);
            vd0 = __fmaf_rn(0.1f, __fsub_rn(i0, v0), v0);
            vd1 = __fmaf_rn(0.1f, __fsub_rn(i1, v1), v1);
            bool z0 = __fsub_rn(vd0, 1.0f) > 0.0f; v0 = z0 ? 0.f : vd0;
            bool z1 = __fsub_rn(vd1, 1.0f) > 0.0f; v1 = z1 ? 0.f : vd1;

            float e0 = u0, e1 = u1;      // com-sum continues in ascending k
            float g0 = 0.f, g1 = 0.f;    // z_a @ Wcrec
            {
                unsigned m = (unsigned)zam;
                while (m) { int k = __ffs(m) - 1; m &= m - 1;
                            float4 w = wc2[k * 32];
                            e0 = __fadd_rn(e0, w.x); e1 = __fadd_rn(e1, w.y);
                            g0 = __fadd_rn(g0, w.z); g1 = __fadd_rn(g1, w.w); }
                m = (unsigned)(zam >> 32);
                while (m) { int k = __ffs(m) - 1 + 32; m &= m - 1;
                            float4 w = wc2[k * 32];
                            e0 = __fadd_rn(e0, w.x); e1 = __fadd_rn(e1, w.y);
                            g0 = __fadd_rn(g0, w.z); g1 = __fadd_rn(g1, w.w); }
            }
            i0 = __fadd_rn(__fadd_rn(id0, e0), g0);
            i1 = __fadd_rn(__fadd_rn(id1, e1), g1);

            unsigned zlo = __ballot_sync(FULLM, z0);
            unsigned zhi = __ballot_sync(FULLM, z1);
            zm = (unsigned long long)zlo | ((unsigned long long)zhi << 32);

            // ---- LI readout ----
            vli = __fmaf_rn(0.1f, __fsub_rn(ili, vli), vli);
            float ro = 0.f;
            {
                unsigned m = zlo;
                while (m) { int k = __ffs(m) - 1; m &= m - 1; ro = __fadd_rn(ro, w_ro[k]); }
                m = zhi;
                while (m) { int k = __ffs(m) - 1; m &= m - 1; ro = __fadd_rn(ro, w_ro[k + 32]); }
            }
            ili = __fadd_rn(__fmaf_rn(-0.2f, ili, ili), ro);
            vmax = fmaxf(vmax, vli);
        }

        if (lane == 0) out[b] = vmax;

        if (lane == 0) b = atomicAdd(&g_ticket, 1u);
        b = __shfl_sync(FULLM, b, 0);
    }
}

extern "C" void kernel_launch(void* const* d_in, const int* in_sizes, int n_in,
                              void* d_out, int out_size)
{
    const float* state  = (const float*)d_in[0];
    const float* action = (const float*)d_in[1];
    const float* Wsin   = (const float*)d_in[2];
    const float* Wsrec  = (const float*)d_in[3];
    const float* Wain   = (const float*)d_in[4];
    const float* Warec  = (const float*)d_in[5];
    const float* Wcin   = (const float*)d_in[6];
    const float* Wcrec  = (const float*)d_in[7];
    const float* Wro    = (const float*)d_in[8];

    int sms = 148;
    cudaDeviceGetAttribute(&sms, cudaDevAttrMultiProcessorCount, 0);
    int grid = sms * 2;
    unsigned nwarps = (unsigned)grid * 16u;

    cudaFuncSetAttribute(snn_kernel, cudaFuncAttributeMaxDynamicSharedMemorySize,
                         SMEM_FLOATS * sizeof(float));

    reset_ticket_kernel<<<1, 1>>>(nwarps);
    snn_kernel<<<grid, 512, SMEM_FLOATS * sizeof(float)>>>(
        state, action, Wsin, Wsrec, Wain, Warec, Wcin, Wcrec, Wro, (float*)d_out);
}

// round 5
// speedup vs baseline: 1.9277x; 1.9277x over previous
#include <cuda_runtime.h>
#include <cstdint>

#define FULLM 0xffffffffu

constexpr int Bsz  = 16384;
constexpr int Sdim = 24;
constexpr int Adim = 4;
constexpr int Tlen = 40;

// ---- shared memory layout (float offsets) ----
// ws_in  : float2 [48][32]  (Wsin[l][k], Wsin[l+32][k]) at [k*32+l]
// ws_rec : float2 [64][32]
// wa_in  : float2 [8][32]
// warc1  : float4 [64][32]  (Warec[l][k], Warec[l+32][k], Wcin[l][k], Wcin[l+32][k])
// wc2r   : float2 [64][32]  (Wcin[l][64+k]+Wcrec[l][k], same for l+32)  [merged]
// w_ro   : float [64]
#define OFF_WSIN   0
#define OFF_WSREC  3072
#define OFF_WAIN   7168
#define OFF_WARC1  7680
#define OFF_WC2R   15872
#define OFF_WRO    19968
#define SMEM_FLOATS 20032

__device__ unsigned g_ticket;

__global__ void reset_ticket_kernel(unsigned start) { g_ticket = start; }

__global__ void __launch_bounds__(512, 2)
snn_kernel(const float* __restrict__ state, const float* __restrict__ action,
           const float* __restrict__ Wsin, const float* __restrict__ Wsrec,
           const float* __restrict__ Wain, const float* __restrict__ Warec,
           const float* __restrict__ Wcin, const float* __restrict__ Wcrec,
           const float* __restrict__ Wro, float* __restrict__ out)
{
    extern __shared__ float smem[];
    const int tid = threadIdx.x;

    // ---- cooperative weight load / transpose (exact fp32) ----
    for (int idx = tid; idx < 48 * 32; idx += 512) {
        int k = idx >> 5, l = idx & 31;
        smem[OFF_WSIN + k * 64 + 2 * l]     = Wsin[l * 48 + k];
        smem[OFF_WSIN + k * 64 + 2 * l + 1] = Wsin[(l + 32) * 48 + k];
    }
    for (int idx = tid; idx < 64 * 32; idx += 512) {
        int k = idx >> 5, l = idx & 31;
        smem[OFF_WSREC + k * 64 + 2 * l]     = Wsrec[l * 64 + k];
        smem[OFF_WSREC + k * 64 + 2 * l + 1] = Wsrec[(l + 32) * 64 + k];
        float4 w4;
        w4.x = Warec[l * 64 + k];
        w4.y = Warec[(l + 32) * 64 + k];
        w4.z = Wcin[l * 128 + k];
        w4.w = Wcin[(l + 32) * 128 + k];
        reinterpret_cast<float4*>(smem + OFF_WARC1)[k * 32 + l] = w4;
        // merged Wcin[:,64+k] + Wcrec[:,k] (both multiply z_a; ~1e-7 reorder, flip-free)
        smem[OFF_WC2R + k * 64 + 2 * l]     = __fadd_rn(Wcin[l * 128 + 64 + k],        Wcrec[l * 64 + k]);
        smem[OFF_WC2R + k * 64 + 2 * l + 1] = __fadd_rn(Wcin[(l + 32) * 128 + 64 + k], Wcrec[(l + 32) * 64 + k]);
    }
    for (int idx = tid; idx < 8 * 32; idx += 512) {
        int k = idx >> 5, l = idx & 31;
        smem[OFF_WAIN + k * 64 + 2 * l]     = Wain[l * 8 + k];
        smem[OFF_WAIN + k * 64 + 2 * l + 1] = Wain[(l + 32) * 8 + k];
    }
    if (tid < 64) smem[OFF_WRO + tid] = Wro[tid];
    __syncthreads();

    const int lane = tid & 31;
    const float2* ws_in  = reinterpret_cast<const float2*>(smem + OFF_WSIN)  + lane;
    const float2* ws_rec = reinterpret_cast<const float2*>(smem + OFF_WSREC) + lane;
    const float2* wa_in  = reinterpret_cast<const float2*>(smem + OFF_WAIN)  + lane;
    const float4* warc1  = reinterpret_cast<const float4*>(smem + OFF_WARC1) + lane;
    const float2* wc2r   = reinterpret_cast<const float2*>(smem + OFF_WC2R)  + lane;
    const float*  w_ro   = smem + OFF_WRO;

    unsigned b = blockIdx.x * 16u + (unsigned)(tid >> 5);

    while (b < (unsigned)Bsz) {
        const float* srow = state  + (size_t)b * Sdim;
        const float* arow = action + (size_t)b * Adim;

        float c0, c1;
        if (lane < 24) c0 = fmaxf(__fmul_rn(50.f, srow[lane]), 0.f);
        else           c0 = fmaxf(__fmul_rn(-50.f, srow[lane - 24]), 0.f);
        if (lane < 16)      c1 = fmaxf(__fmul_rn(-50.f, srow[8 + lane]), 0.f);
        else if (lane < 20) c1 = fmaxf(__fmul_rn(50.f, arow[lane - 16]), 0.f);
        else if (lane < 24) c1 = fmaxf(__fmul_rn(-50.f, arow[lane - 20]), 0.f);
        else                c1 = 0.f;

        // "always-spiking" features: from ve=0 the first update gives rn(0.1*c);
        // spike iff >1 (then reset to 0) -> repeats identically every step.
        bool alw0 = __fmul_rn(0.1f, c0) > 1.0f;
        bool alw1 = (lane < 24) && (__fmul_rn(0.1f, c1) > 1.0f);
        unsigned alo = __ballot_sync(FULLM, alw0);
        unsigned ahi = __ballot_sync(FULLM, alw1);
        unsigned long long xs_always = (unsigned long long)alo |
                                       ((unsigned long long)(ahi & 0xFFFFu) << 32);
        unsigned xa_always = (ahi >> 16) & 0xFFu;

        // hoisted base sums over always-on inputs (reused all 40 steps)
        float bs0 = 0.f, bs1 = 0.f;
        {
            unsigned m = (unsigned)xs_always;
            while (m) { int k = __ffs(m) - 1; m &= m - 1;
                        float2 w = ws_in[k * 32]; bs0 += w.x; bs1 += w.y; }
            m = (unsigned)(xs_always >> 32);
            while (m) { int k = __ffs(m) - 1 + 32; m &= m - 1;
                        float2 w = ws_in[k * 32]; bs0 += w.x; bs1 += w.y; }
        }
        float ba0 = 0.f, ba1 = 0.f;
        {
            unsigned m = xa_always;
            while (m) { int k = __ffs(m) - 1; m &= m - 1;
                        float2 w = wa_in[k * 32]; ba0 += w.x; ba1 += w.y; }
        }

        float ve0 = 0.f, ve1 = 0.f;
        float v0 = 0.f, v1 = 0.f;
        float i0 = 0.f, i1 = 0.f;
        unsigned long long zm = 0ull;
        float vli = 0.f, ili = 0.f;
        float vmax = -3.0e38f;

        for (int t = 0; t < Tlen; t++) {
            // ---- encoder step (FMA-contracted like XLA) ----
            ve0 = __fmaf_rn(0.1f, __fsub_rn(c0, ve0), ve0);
            bool s0 = __fsub_rn(ve0, 1.0f) > 0.0f; if (s0) ve0 = 0.f;
            ve1 = __fmaf_rn(0.1f, __fsub_rn(c1, ve1), ve1);
            bool s1 = (lane < 24) && (__fsub_rn(ve1, 1.0f) > 0.0f); if (s1) ve1 = 0.f;
            unsigned mlo = __ballot_sync(FULLM, s0);
            unsigned mhi = __ballot_sync(FULLM, s1);
            unsigned long long xs = (unsigned long long)mlo |
                                    ((unsigned long long)(mhi & 0xFFFFu) << 32);
            unsigned xa = (mhi >> 16) & 0xFFu;

            // ---- lif1 ----
            float id0 = __fmaf_rn(-0.2f, i0, i0);
            float id1 = __fmaf_rn(-0.2f, i1, i1);
            float vd0 = __fmaf_rn(0.1f, __fsub_rn(i0, v0), v0);
            float vd1 = __fmaf_rn(0.1f, __fsub_rn(i1, v1), v1);
            bool zs0 = __fsub_rn(vd0, 1.0f) > 0.0f; v0 = zs0 ? 0.f : vd0;
            bool zs1 = __fsub_rn(vd1, 1.0f) > 0.0f; v1 = zs1 ? 0.f : vd1;

            float a0 = bs0, a1 = bs1;
            unsigned long long dev = xs & ~xs_always;
            {
                unsigned m = (unsigned)dev;
                while (m) { int k = __ffs(m) - 1; m &= m - 1;
                            float2 w = ws_in[k * 32];
                            a0 = __fadd_rn(a0, w.x); a1 = __fadd_rn(a1, w.y); }
                m = (unsigned)(dev >> 32);
                while (m) { int k = __ffs(m) - 1 + 32; m &= m - 1;
                            float2 w = ws_in[k * 32];
                            a0 = __fadd_rn(a0, w.x); a1 = __fadd_rn(a1, w.y); }
            }
            float r0 = 0.f, r1 = 0.f;
            {
                unsigned m = (unsigned)zm;
                while (m) { int k = __ffs(m) - 1; m &= m - 1;
                            float2 w = ws_rec[k * 32];
                            r0 = __fadd_rn(r0, w.x); r1 = __fadd_rn(r1, w.y); }
                m = (unsigned)(zm >> 32);
                while (m) { int k = __ffs(m) - 1 + 32; m &= m - 1;
                            float2 w = ws_rec[k * 32];
                            r0 = __fadd_rn(r0, w.x); r1 = __fadd_rn(r1, w.y); }
            }
            i0 = __fadd_rn(__fadd_rn(id0, a0), r0);
            i1 = __fadd_rn(__fadd_rn(id1, a1), r1);

            unsigned zslo = __ballot_sync(FULLM, zs0);
            unsigned zshi = __ballot_sync(FULLM, zs1);
            unsigned long long zsm = (unsigned long long)zslo | ((unsigned long long)zshi << 32);

            // ---- lif2 (+ gather Wcin[:, :64]·z_s for lif3) ----
            id0 = __fmaf_rn(-0.2f, i0, i0);
            id1 = __fmaf_rn(-0.2f, i1, i1);
            vd0 = __fmaf_rn(0.1f, __fsub_rn(i0, v0), v0);
            vd1 = __fmaf_rn(0.1f, __fsub_rn(i1, v1), v1);
            bool za0 = __fsub_rn(vd0, 1.0f) > 0.0f; v0 = za0 ? 0.f : vd0;
            bool za1 = __fsub_rn(vd1, 1.0f) > 0.0f; v1 = za1 ? 0.f : vd1;

            float p0 = ba0, p1 = ba1;
            {
                unsigned m = xa & ~xa_always;
                while (m) { int k = __ffs(m) - 1; m &= m - 1;
                            float2 w = wa_in[k * 32];
                            p0 = __fadd_rn(p0, w.x); p1 = __fadd_rn(p1, w.y); }
            }
            float q0 = 0.f, q1 = 0.f, u0 = 0.f, u1 = 0.f;
            {
                unsigned m = (unsigned)zsm;
                while (m) { int k = __ffs(m) - 1; m &= m - 1;
                            float4 w = warc1[k * 32];
                            q0 = __fadd_rn(q0, w.x); q1 = __fadd_rn(q1, w.y);
                            u0 = __fadd_rn(u0, w.z); u1 = __fadd_rn(u1, w.w); }
                m = (unsigned)(zsm >> 32);
                while (m) { int k = __ffs(m) - 1 + 32; m &= m - 1;
                            float4 w = warc1[k * 32];
                            q0 = __fadd_rn(q0, w.x); q1 = __fadd_rn(q1, w.y);
                            u0 = __fadd_rn(u0, w.z); u1 = __fadd_rn(u1, w.w); }
            }
            i0 = __fadd_rn(__fadd_rn(id0, p0), q0);
            i1 = __fadd_rn(__fadd_rn(id1, p1), q1);

            unsigned zalo = __ballot_sync(FULLM, za0);
            unsigned zahi = __ballot_sync(FULLM, za1);
            unsigned long long zam = (unsigned long long)zalo | ((unsigned long long)zahi << 32);

            // ---- lif3 (merged Wcin2+Wcrec on z_a) ----
            id0 = __fmaf_rn(-0.2f, i0, i0);
            id1 = __fmaf_rn(-0.2f, i1, i1);
            vd0 = __fmaf_rn(0.1f, __fsub_rn(i0, v0), v0);
            vd1 = __fmaf_rn(0.1f, __fsub_rn(i1, v1), v1);
            bool z0 = __fsub_rn(vd0, 1.0f) > 0.0f; v0 = z0 ? 0.f : vd0;
            bool z1 = __fsub_rn(vd1, 1.0f) > 0.0f; v1 = z1 ? 0.f : vd1;

            float e0 = u0, e1 = u1;
            {
                unsigned m = (unsigned)zam;
                while (m) { int k = __ffs(m) - 1; m &= m - 1;
                            float2 w = wc2r[k * 32];
                            e0 = __fadd_rn(e0, w.x); e1 = __fadd_rn(e1, w.y); }
                m = (unsigned)(zam >> 32);
                while (m) { int k = __ffs(m) - 1 + 32; m &= m - 1;
                            float2 w = wc2r[k * 32];
                            e0 = __fadd_rn(e0, w.x); e1 = __fadd_rn(e1, w.y); }
            }
            i0 = __fadd_rn(id0, e0);
            i1 = __fadd_rn(id1, e1);

            unsigned zlo = __ballot_sync(FULLM, z0);
            unsigned zhi = __ballot_sync(FULLM, z1);
            zm = (unsigned long long)zlo | ((unsigned long long)zhi << 32);

            // ---- LI readout ----
            vli = __fmaf_rn(0.1f, __fsub_rn(ili, vli), vli);
            float ro = 0.f;
            {
                unsigned m = zlo;
                while (m) { int k = __ffs(m) - 1; m &= m - 1; ro = __fadd_rn(ro, w_ro[k]); }
                m = zhi;
                while (m) { int k = __ffs(m) - 1; m &= m - 1; ro = __fadd_rn(ro, w_ro[k + 32]); }
            }
            ili = __fadd_rn(__fmaf_rn(-0.2f, ili, ili), ro);
            vmax = fmaxf(vmax, vli);
        }

        if (lane == 0) out[b] = vmax;

        if (lane == 0) b = atomicAdd(&g_ticket, 1u);
        b = __shfl_sync(FULLM, b, 0);
    }
}

extern "C" void kernel_launch(void* const* d_in, const int* in_sizes, int n_in,
                              void* d_out, int out_size)
{
    const float* state  = (const float*)d_in[0];
    const float* action = (const float*)d_in[1];
    const float* Wsin   = (const float*)d_in[2];
    const float* Wsrec  = (const float*)d_in[3];
    const float* Wain   = (const float*)d_in[4];
    const float* Warec  = (const float*)d_in[5];
    const float* Wcin   = (const float*)d_in[6];
    const float* Wcrec  = (const float*)d_in[7];
    const float* Wro    = (const float*)d_in[8];

    int sms = 148;
    cudaDeviceGetAttribute(&sms, cudaDevAttrMultiProcessorCount, 0);
    int grid = sms * 2;
    unsigned nwarps = (unsigned)grid * 16u;

    cudaFuncSetAttribute(snn_kernel, cudaFuncAttributeMaxDynamicSharedMemorySize,
                         SMEM_FLOATS * sizeof(float));

    reset_ticket_kernel<<<1, 1>>>(nwarps);
    snn_kernel<<<grid, 512, SMEM_FLOATS * sizeof(float)>>>(
        state, action, Wsin, Wsrec, Wain, Warec, Wcin, Wcrec, Wro, (float*)d_out);
}

// round 7
// speedup vs baseline: 1.9853x; 1.0299x over previous
#include <cuda_runtime.h>
#include <cstdint>

#define FULLM 0xffffffffu

constexpr int Bsz  = 16384;
constexpr int Sdim = 24;
constexpr int Adim = 4;
constexpr int Tlen = 40;

// ---- shared memory layout (float offsets) ----
// wsain4 : float4 [56][32]  k<48: (Wsin[l][k], Wsin[l+32][k], 0, 0)
//                           k>=48:(0, 0, Wain[l][k-48], Wain[l+32][k-48])
// wsrec4 : float4 [64][32]  (Wsrec[l][k], Wsrec[l+32][k], Wro[k], 0)
// warc1  : float4 [64][32]  (Warec[l][k], Warec[l+32][k], Wcin[l][k], Wcin[l+32][k])
// wc2r   : float2 [64][32]  (Wcin[l][64+k]+Wcrec[l][k], same for l+32) [merged]
#define OFF_WSAIN  0
#define OFF_WSREC4 7168
#define OFF_WARC1  15360
#define OFF_WC2R   23552
#define SMEM_FLOATS 27648

__device__ unsigned g_ticket;

__global__ void reset_ticket_kernel(unsigned start) { g_ticket = start; }

__global__ void __launch_bounds__(512, 2)
snn_kernel(const float* __restrict__ state, const float* __restrict__ action,
           const float* __restrict__ Wsin, const float* __restrict__ Wsrec,
           const float* __restrict__ Wain, const float* __restrict__ Warec,
           const float* __restrict__ Wcin, const float* __restrict__ Wcrec,
           const float* __restrict__ Wro, float* __restrict__ out)
{
    extern __shared__ float smem[];
    const int tid = threadIdx.x;

    // ---- cooperative weight load / transpose (exact fp32) ----
    for (int idx = tid; idx < 56 * 32; idx += 512) {
        int k = idx >> 5, l = idx & 31;
        float4 w4;
        if (k < 48) { w4.x = Wsin[l * 48 + k]; w4.y = Wsin[(l + 32) * 48 + k]; w4.z = 0.f; w4.w = 0.f; }
        else        { w4.x = 0.f; w4.y = 0.f; w4.z = Wain[l * 8 + (k - 48)]; w4.w = Wain[(l + 32) * 8 + (k - 48)]; }
        reinterpret_cast<float4*>(smem + OFF_WSAIN)[k * 32 + l] = w4;
    }
    for (int idx = tid; idx < 64 * 32; idx += 512) {
        int k = idx >> 5, l = idx & 31;
        float4 s4;
        s4.x = Wsrec[l * 64 + k];
        s4.y = Wsrec[(l + 32) * 64 + k];
        s4.z = Wro[k];
        s4.w = 0.f;
        reinterpret_cast<float4*>(smem + OFF_WSREC4)[k * 32 + l] = s4;
        float4 w4;
        w4.x = Warec[l * 64 + k];
        w4.y = Warec[(l + 32) * 64 + k];
        w4.z = Wcin[l * 128 + k];
        w4.w = Wcin[(l + 32) * 128 + k];
        reinterpret_cast<float4*>(smem + OFF_WARC1)[k * 32 + l] = w4;
        // merged Wcin[:,64+k] + Wcrec[:,k] (both multiply z_a; reorder is flip-free)
        smem[OFF_WC2R + k * 64 + 2 * l]     = __fadd_rn(Wcin[l * 128 + 64 + k],        Wcrec[l * 64 + k]);
        smem[OFF_WC2R + k * 64 + 2 * l + 1] = __fadd_rn(Wcin[(l + 32) * 128 + 64 + k], Wcrec[(l + 32) * 64 + k]);
    }
    __syncthreads();

    const int lane = tid & 31;
    const float4* wsain  = reinterpret_cast<const float4*>(smem + OFF_WSAIN)  + lane;
    const float4* wsrec4 = reinterpret_cast<const float4*>(smem + OFF_WSREC4) + lane;
    const float4* warc1  = reinterpret_cast<const float4*>(smem + OFF_WARC1)  + lane;
    const float2* wc2r   = reinterpret_cast<const float2*>(smem + OFF_WC2R)   + lane;

    unsigned b = blockIdx.x * 16u + (unsigned)(tid >> 5);

    while (b < (unsigned)Bsz) {
        const float* srow = state  + (size_t)b * Sdim;
        const float* arow = action + (size_t)b * Adim;

        float c0, c1;
        if (lane < 24) c0 = fmaxf(__fmul_rn(50.f, srow[lane]), 0.f);
        else           c0 = fmaxf(__fmul_rn(-50.f, srow[lane - 24]), 0.f);
        if (lane < 16)      c1 = fmaxf(__fmul_rn(-50.f, srow[8 + lane]), 0.f);
        else if (lane < 20) c1 = fmaxf(__fmul_rn(50.f, arow[lane - 16]), 0.f);
        else if (lane < 24) c1 = fmaxf(__fmul_rn(-50.f, arow[lane - 20]), 0.f);
        else                c1 = 0.f;

        // always-spiking features (spike identically every step)
        bool alw0 = __fmul_rn(0.1f, c0) > 1.0f;
        bool alw1 = (lane < 24) && (__fmul_rn(0.1f, c1) > 1.0f);
        unsigned alo = __ballot_sync(FULLM, alw0);
        unsigned ahi = __ballot_sync(FULLM, alw1);
        // combined 56-bit input mask: bits 0..47 = xs, bits 48..55 = xa
        unsigned long long x_always = (unsigned long long)alo | ((unsigned long long)ahi << 32);

        // hoisted base sums over always-on inputs (bs: lif1 input, ba: lif2 input)
        float bs0 = 0.f, bs1 = 0.f, ba0 = 0.f, ba1 = 0.f;
        {
            unsigned m = (unsigned)x_always;
            while (m) { int k = __ffs(m) - 1; m &= m - 1;
                        float4 w = wsain[k * 32];
                        bs0 += w.x; bs1 += w.y; ba0 += w.z; ba1 += w.w; }
            m = (unsigned)(x_always >> 32);
            while (m) { int k = __ffs(m) - 1 + 32; m &= m - 1;
                        float4 w = wsain[k * 32];
                        bs0 += w.x; bs1 += w.y; ba0 += w.z; ba1 += w.w; }
        }

        float ve0 = 0.f, ve1 = 0.f;
        float v0 = 0.f, v1 = 0.f;
        float i0 = 0.f, i1 = 0.f;
        float r0 = 0.f, r1 = 0.f;           // z_prev @ Wsrec (carried from prev step)
        float vli = 0.f, ili = 0.f;
        float vmax = -3.0e38f;

        for (int t = 0; t < Tlen; t++) {
            // ---- encoder step (FMA-contracted like XLA) ----
            ve0 = __fmaf_rn(0.1f, __fsub_rn(c0, ve0), ve0);
            bool s0 = __fsub_rn(ve0, 1.0f) > 0.0f; if (s0) ve0 = 0.f;
            ve1 = __fmaf_rn(0.1f, __fsub_rn(c1, ve1), ve1);
            bool s1 = (lane < 24) && (__fsub_rn(ve1, 1.0f) > 0.0f); if (s1) ve1 = 0.f;
            unsigned mlo = __ballot_sync(FULLM, s0);
            unsigned mhi = __ballot_sync(FULLM, s1);
            unsigned long long xall = (unsigned long long)mlo | ((unsigned long long)mhi << 32);

            // ---- lif1 (input dev-walk; recurrent r carried from prev step) ----
            float id0 = __fmaf_rn(-0.2f, i0, i0);
            float id1 = __fmaf_rn(-0.2f, i1, i1);
            float vd0 = __fmaf_rn(0.1f, __fsub_rn(i0, v0), v0);
            float vd1 = __fmaf_rn(0.1f, __fsub_rn(i1, v1), v1);
            bool zs0 = __fsub_rn(vd0, 1.0f) > 0.0f; v0 = zs0 ? 0.f : vd0;
            bool zs1 = __fsub_rn(vd1, 1.0f) > 0.0f; v1 = zs1 ? 0.f : vd1;

            float a0 = bs0, a1 = bs1, p0 = ba0, p1 = ba1;
            unsigned long long dev = xall & ~x_always;
            {
                unsigned m = (unsigned)dev;
                while (m) { int k = __ffs(m) - 1; m &= m - 1;
                            float4 w = wsain[k * 32];
                            a0 = __fadd_rn(a0, w.x); a1 = __fadd_rn(a1, w.y);
                            p0 = __fadd_rn(p0, w.z); p1 = __fadd_rn(p1, w.w); }
                m = (unsigned)(dev >> 32);
                while (m) { int k = __ffs(m) - 1 + 32; m &= m - 1;
                            float4 w = wsain[k * 32];
                            a0 = __fadd_rn(a0, w.x); a1 = __fadd_rn(a1, w.y);
                            p0 = __fadd_rn(p0, w.z); p1 = __fadd_rn(p1, w.w); }
            }
            i0 = __fadd_rn(__fadd_rn(id0, a0), r0);
            i1 = __fadd_rn(__fadd_rn(id1, a1), r1);

            unsigned zslo = __ballot_sync(FULLM, zs0);
            unsigned zshi = __ballot_sync(FULLM, zs1);
            unsigned long long zsm = (unsigned long long)zslo | ((unsigned long long)zshi << 32);

            // ---- lif2 (+ gather Wcin[:, :64]·z_s for lif3) ----
            id0 = __fmaf_rn(-0.2f, i0, i0);
            id1 = __fmaf_rn(-0.2f, i1, i1);
            vd0 = __fmaf_rn(0.1f, __fsub_rn(i0, v0), v0);
            vd1 = __fmaf_rn(0.1f, __fsub_rn(i1, v1), v1);
            bool za0 = __fsub_rn(vd0, 1.0f) > 0.0f; v0 = za0 ? 0.f : vd0;
            bool za1 = __fsub_rn(vd1, 1.0f) > 0.0f; v1 = za1 ? 0.f : vd1;

            float q0 = 0.f, q1 = 0.f, u0 = 0.f, u1 = 0.f;
            {
                unsigned m = (unsigned)zsm;
                while (m) { int k = __ffs(m) - 1; m &= m - 1;
                            float4 w = warc1[k * 32];
                            q0 = __fadd_rn(q0, w.x); q1 = __fadd_rn(q1, w.y);
                            u0 = __fadd_rn(u0, w.z); u1 = __fadd_rn(u1, w.w); }
                m = (unsigned)(zsm >> 32);
                while (m) { int k = __ffs(m) - 1 + 32; m &= m - 1;
                            float4 w = warc1[k * 32];
                            q0 = __fadd_rn(q0, w.x); q1 = __fadd_rn(q1, w.y);
                            u0 = __fadd_rn(u0, w.z); u1 = __fadd_rn(u1, w.w); }
            }
            i0 = __fadd_rn(__fadd_rn(id0, p0), q0);
            i1 = __fadd_rn(__fadd_rn(id1, p1), q1);

            unsigned zalo = __ballot_sync(FULLM, za0);
            unsigned zahi = __ballot_sync(FULLM, za1);
            unsigned long long zam = (unsigned long long)zalo | ((unsigned long long)zahi << 32);

            // ---- lif3 (merged Wcin2+Wcrec on z_a) ----
            id0 = __fmaf_rn(-0.2f, i0, i0);
            id1 = __fmaf_rn(-0.2f, i1, i1);
            vd0 = __fmaf_rn(0.1f, __fsub_rn(i0, v0), v0);
            vd1 = __fmaf_rn(0.1f, __fsub_rn(i1, v1), v1);
            bool z0 = __fsub_rn(vd0, 1.0f) > 0.0f; v0 = z0 ? 0.f : vd0;
            bool z1 = __fsub_rn(vd1, 1.0f) > 0.0f; v1 = z1 ? 0.f : vd1;

            float e0 = u0, e1 = u1;
            {
                unsigned m = (unsigned)zam;
                while (m) { int k = __ffs(m) - 1; m &= m - 1;
                            float2 w = wc2r[k * 32];
                            e0 = __fadd_rn(e0, w.x); e1 = __fadd_rn(e1, w.y); }
                m = (unsigned)(zam >> 32);
                while (m) { int k = __ffs(m) - 1 + 32; m &= m - 1;
                            float2 w = wc2r[k * 32];
                            e0 = __fadd_rn(e0, w.x); e1 = __fadd_rn(e1, w.y); }
            }
            i0 = __fadd_rn(id0, e0);
            i1 = __fadd_rn(id1, e1);

            unsigned zlo = __ballot_sync(FULLM, z0);
            unsigned zhi = __ballot_sync(FULLM, z1);
            unsigned long long zm = (unsigned long long)zlo | ((unsigned long long)zhi << 32);

            // ---- combined walk over fresh zm: next-step recurrent (r) + readout (ro) ----
            float nr0 = 0.f, nr1 = 0.f, ro = 0.f;
            {
                unsigned m = (unsigned)zm;
                while (m) { int k = __ffs(m) - 1; m &= m - 1;
                            float4 w = wsrec4[k * 32];
                            nr0 = __fadd_rn(nr0, w.x); nr1 = __fadd_rn(nr1, w.y);
                            ro  = __fadd_rn(ro,  w.z); }
                m = (unsigned)(zm >> 32);
                while (m) { int k = __ffs(m) - 1 + 32; m &= m - 1;
                            float4 w = wsrec4[k * 32];
                            nr0 = __fadd_rn(nr0, w.x); nr1 = __fadd_rn(nr1, w.y);
                            ro  = __fadd_rn(ro,  w.z); }
            }
            r0 = nr0; r1 = nr1;

            // ---- LI readout ----
            vli = __fmaf_rn(0.1f, __fsub_rn(ili, vli), vli);
            ili = __fadd_rn(__fmaf_rn(-0.2f, ili, ili), ro);
            vmax = fmaxf(vmax, vli);
        }

        if (lane == 0) out[b] = vmax;

        if (lane == 0) b = atomicAdd(&g_ticket, 1u);
        b = __shfl_sync(FULLM, b, 0);
    }
}

extern "C" void kernel_launch(void* const* d_in, const int* in_sizes, int n_in,
                              void* d_out, int out_size)
{
    const float* state  = (const float*)d_in[0];
    const float* action = (const float*)d_in[1];
    const float* Wsin   = (const float*)d_in[2];
    const float* Wsrec  = (const float*)d_in[3];
    const float* Wain   = (const float*)d_in[4];
    const float* Warec  = (const float*)d_in[5];
    const float* Wcin   = (const float*)d_in[6];
    const float* Wcrec  = (const float*)d_in[7];
    const float* Wro    = (const float*)d_in[8];

    int sms = 148;
    cudaDeviceGetAttribute(&sms, cudaDevAttrMultiProcessorCount, 0);
    int grid = sms * 2;
    unsigned nwarps = (unsigned)grid * 16u;

    cudaFuncSetAttribute(snn_kernel, cudaFuncAttributeMaxDynamicSharedMemorySize,
                         SMEM_FLOATS * sizeof(float));

    reset_ticket_kernel<<<1, 1>>>(nwarps);
    snn_kernel<<<grid, 512, SMEM_FLOATS * sizeof(float)>>>(
        state, action, Wsin, Wsrec, Wain, Warec, Wcin, Wcrec, Wro, (float*)d_out);
}